// round 5
// baseline (speedup 1.0000x reference)
#include <cuda_runtime.h>
#include <cuda_bf16.h>
#include <cstdint>
#include <math.h>

#define BATCH 2
#define TSEQ  4096
#define NH    16
#define HD    64
#define CEMB  1024
#define MROWS (BATCH*TSEQ)          // 8192
#define SCALE 0.125f                // 1/sqrt(64)

// ---------------- scratch (device globals: no runtime allocation) ------------
__device__ __nv_bfloat16 g_xh[(size_t)MROWS*CEMB];
__device__ __nv_bfloat16 g_xl[(size_t)MROWS*CEMB];
__device__ __nv_bfloat16 g_yh[(size_t)MROWS*CEMB];
__device__ __nv_bfloat16 g_yl[(size_t)MROWS*CEMB];
__device__ __nv_bfloat16 g_wqh[(size_t)3*CEMB*CEMB];   // [N,K] K-major
__device__ __nv_bfloat16 g_wql[(size_t)3*CEMB*CEMB];
__device__ __nv_bfloat16 g_wph[(size_t)CEMB*CEMB];
__device__ __nv_bfloat16 g_wpl[(size_t)CEMB*CEMB];
__device__ __nv_bfloat16 g_qh[(size_t)BATCH*NH*TSEQ*HD];
__device__ __nv_bfloat16 g_ql[(size_t)BATCH*NH*TSEQ*HD];
__device__ __nv_bfloat16 g_kh[(size_t)BATCH*NH*TSEQ*HD];
__device__ __nv_bfloat16 g_kl[(size_t)BATCH*NH*TSEQ*HD];
__device__ __nv_bfloat16 g_vh[(size_t)BATCH*NH*TSEQ*HD];
__device__ __nv_bfloat16 g_vl[(size_t)BATCH*NH*TSEQ*HD];

// ---------------- PTX helpers (sm_80-era only) --------------------------------
__device__ __forceinline__ uint32_t smem_u32(const void* p) {
    uint32_t a;
    asm("{ .reg .u64 t; cvta.to.shared.u64 t, %1; cvt.u32.u64 %0, t; }"
        : "=r"(a) : "l"(p));
    return a;
}
__device__ __forceinline__ void cpasync16(uint32_t saddr, const void* g) {
    asm volatile("cp.async.cg.shared.global [%0], [%1], 16;"
                 :: "r"(saddr), "l"(g) : "memory");
}
#define CP_COMMIT() asm volatile("cp.async.commit_group;" ::: "memory")
#define CP_WAIT1()  asm volatile("cp.async.wait_group 1;" ::: "memory")
#define CP_WAIT0()  asm volatile("cp.async.wait_group 0;" ::: "memory")

__device__ __forceinline__ void ldmx4(uint32_t* r, uint32_t addr) {
    asm volatile("ldmatrix.sync.aligned.m8n8.x4.shared.b16 {%0,%1,%2,%3}, [%4];"
        : "=r"(r[0]), "=r"(r[1]), "=r"(r[2]), "=r"(r[3]) : "r"(addr));
}
__device__ __forceinline__ void ldmx2(uint32_t* r, uint32_t addr) {
    asm volatile("ldmatrix.sync.aligned.m8n8.x2.shared.b16 {%0,%1}, [%2];"
        : "=r"(r[0]), "=r"(r[1]) : "r"(addr));
}
__device__ __forceinline__ void ldmx4t(uint32_t* r, uint32_t addr) {
    asm volatile("ldmatrix.sync.aligned.m8n8.x4.trans.shared.b16 {%0,%1,%2,%3}, [%4];"
        : "=r"(r[0]), "=r"(r[1]), "=r"(r[2]), "=r"(r[3]) : "r"(addr));
}
__device__ __forceinline__ void mma16816(float* d, const uint32_t* a,
                                         const uint32_t* b) {
    asm volatile(
        "mma.sync.aligned.m16n8k16.row.col.f32.bf16.bf16.f32 "
        "{%0,%1,%2,%3}, {%4,%5,%6,%7}, {%8,%9}, {%0,%1,%2,%3};"
        : "+f"(d[0]), "+f"(d[1]), "+f"(d[2]), "+f"(d[3])
        : "r"(a[0]), "r"(a[1]), "r"(a[2]), "r"(a[3]), "r"(b[0]), "r"(b[1]));
}

__device__ __forceinline__ float2 bf2f(uint32_t u) {
    __nv_bfloat162 b = *(__nv_bfloat162*)&u;
    return __bfloat1622float2(b);
}
__device__ __forceinline__ uint32_t packbf(float x, float y) {
    __nv_bfloat162 t = __floats2bfloat162_rn(x, y);
    return *(uint32_t*)&t;
}
__device__ __forceinline__ void split1(float v, unsigned short& h, unsigned short& l) {
    __nv_bfloat16 hb = __float2bfloat16_rn(v);
    __nv_bfloat16 lb = __float2bfloat16_rn(v - __bfloat162float(hb));
    h = __bfloat16_as_ushort(hb);
    l = __bfloat16_as_ushort(lb);
}

// ---------------- conversion kernels ------------------------------------------
__global__ void conv_split_x(const float* __restrict__ src, int n) {
    int i = (blockIdx.x * 256 + threadIdx.x) * 4;
    if (i < n) {
        float4 v = *(const float4*)&src[i];
        ushort4 h, l;
        split1(v.x, h.x, l.x); split1(v.y, h.y, l.y);
        split1(v.z, h.z, l.z); split1(v.w, h.w, l.w);
        *(ushort4*)&g_xh[i] = h;
        *(ushort4*)&g_xl[i] = l;
    }
}
template <int W>
__global__ void conv_split_T(const float* __restrict__ w, int K, int N) {
    __shared__ float t[32][33];
    __nv_bfloat16* hiT = (W == 0) ? g_wqh : g_wph;
    __nv_bfloat16* loT = (W == 0) ? g_wql : g_wpl;
    int n0 = blockIdx.x * 32, k0 = blockIdx.y * 32;
    int tx = threadIdx.x & 31, ty = threadIdx.x >> 5;
    for (int r = ty; r < 32; r += 8)
        t[r][tx] = w[(size_t)(k0 + r) * N + n0 + tx];
    __syncthreads();
    for (int r = ty; r < 32; r += 8) {
        float v = t[tx][r];
        unsigned short h, l;
        split1(v, h, l);
        size_t o = (size_t)(n0 + r) * K + k0 + tx;
        hiT[o] = __ushort_as_bfloat16(h);
        loT[o] = __ushort_as_bfloat16(l);
    }
}

// ---------------- bf16x3 GEMM on mma.sync -------------------------------------
// CTA tile 256x128, BK=64, 512 threads (16 warps in 4x4), warp tile 64x32,
// 2-stage cp.async double buffer, one __syncthreads per k-iter.
#define BK    64
#define KSTR  72
#define ROWB  (KSTR*2)              // 144 B rows
#define A_MATB (256*ROWB)           // 36864 B (one of Ah/Al)
#define B_MATB (128*ROWB)           // 18432 B (one of Bh/Bl)
#define STAGEB (2*A_MATB + 2*B_MATB)  // 110592 B
#define GSMEM (2*STAGEB)            // 221184 B

template <int MODE>
__global__ __launch_bounds__(512, 1)
void gemm_mma(const float* __restrict__ bias, float* __restrict__ out)
{
    extern __shared__ __align__(16) char sm[];
    uint32_t smb = smem_u32(sm);

    const __nv_bfloat16* Ah = (MODE == 0) ? g_xh : g_yh;
    const __nv_bfloat16* Al = (MODE == 0) ? g_xl : g_yl;
    const __nv_bfloat16* Bh = (MODE == 0) ? g_wqh : g_wph;
    const __nv_bfloat16* Bl = (MODE == 0) ? g_wql : g_wpl;

    int tid = threadIdx.x;
    int wid = tid >> 5, lane = tid & 31;
    int wm = wid >> 2, wn = wid & 3;          // 4 x 4 warps
    int mBase = blockIdx.y * 256, nBase = blockIdx.x * 128;

    float acc[4][4][4];
#pragma unroll
    for (int mi = 0; mi < 4; mi++)
#pragma unroll
        for (int ni = 0; ni < 4; ni++)
#pragma unroll
            for (int q = 0; q < 4; q++) acc[mi][ni][q] = 0.f;

    auto load_stage = [&](int st, int kt) {
        int k0 = kt * BK;
        uint32_t sb = smb + st * STAGEB;
        // A hi/lo: 256 rows x 8 chunks each
#pragma unroll
        for (int c = tid; c < 2048; c += 512) {
            int row = c >> 3, ch = c & 7;
            size_t g = (size_t)(mBase + row) * CEMB + k0 + ch * 8;
            cpasync16(sb + row * ROWB + ch * 16, Ah + g);
            cpasync16(sb + A_MATB + row * ROWB + ch * 16, Al + g);
        }
        // B hi/lo: 128 rows x 8 chunks each
#pragma unroll
        for (int c = tid; c < 1024; c += 512) {
            int row = c >> 3, ch = c & 7;
            size_t g = (size_t)(nBase + row) * CEMB + k0 + ch * 8;
            cpasync16(sb + 2 * A_MATB + row * ROWB + ch * 16, Bh + g);
            cpasync16(sb + 2 * A_MATB + B_MATB + row * ROWB + ch * 16, Bl + g);
        }
    };

    int g = lane >> 3, w = lane & 7;
    uint32_t a_row = (wm * 64 + ((g & 1) << 3) + w) * ROWB;
    uint32_t b_row = (wn * 32 + w) * ROWB;
    uint32_t ka_off = ((g >> 1) << 3) * 2;
    uint32_t kb_off = ((g & 1) << 3) * 2;

    load_stage(0, 0); CP_COMMIT();

    for (int kt = 0; kt < 16; kt++) {
        CP_WAIT0();
        __syncthreads();
        if (kt + 1 < 16) { load_stage((kt + 1) & 1, kt + 1); CP_COMMIT(); }

        int s = kt & 1;
        uint32_t bAh = smb + s * STAGEB;
        uint32_t bAl = bAh + A_MATB;
        uint32_t bBh = bAl + A_MATB;
        uint32_t bBl = bBh + B_MATB;

#pragma unroll
        for (int ks = 0; ks < 4; ks++) {
            uint32_t ka = ks * 32 + ka_off;
            uint32_t kb = ks * 32 + kb_off;
            uint32_t ah[4][4], al[4][4];
#pragma unroll
            for (int mi = 0; mi < 4; mi++) {
                uint32_t ro = a_row + mi * 16 * ROWB;
                ldmx4(ah[mi], bAh + ro + ka);
                ldmx4(al[mi], bAl + ro + ka);
            }
#pragma unroll
            for (int ni = 0; ni < 4; ni++) {
                uint32_t ro = b_row + ni * 8 * ROWB;
                uint32_t bh2[2], bl2[2];
                ldmx2(bh2, bBh + ro + kb);
                ldmx2(bl2, bBl + ro + kb);
#pragma unroll
                for (int mi = 0; mi < 4; mi++) {
                    mma16816(acc[mi][ni], ah[mi], bh2);
                    mma16816(acc[mi][ni], ah[mi], bl2);
                    mma16816(acc[mi][ni], al[mi], bh2);
                }
            }
        }
        __syncthreads();
    }

    // epilogue
    int r_in = lane >> 2, c_in = (lane & 3) * 2;
#pragma unroll
    for (int mi = 0; mi < 4; mi++) {
#pragma unroll
        for (int half = 0; half < 2; half++) {
            int m = mBase + wm * 64 + mi * 16 + r_in + half * 8;
#pragma unroll
            for (int ni = 0; ni < 4; ni++) {
                int n = nBase + wn * 32 + ni * 8 + c_in;
                float v0 = acc[mi][ni][half * 2 + 0] + bias[n];
                float v1 = acc[mi][ni][half * 2 + 1] + bias[n + 1];
                if (MODE == 0) {
                    int b = m >> 12, t = m & 4095;
                    int sect = n >> 10, cc = n & 1023;
                    int head = cc >> 6, d0 = cc & 63;
                    unsigned short h0, l0, h1, l1;
                    split1(v0, h0, l0); split1(v1, h1, l1);
                    uint32_t hv = (uint32_t)h0 | ((uint32_t)h1 << 16);
                    uint32_t lv = (uint32_t)l0 | ((uint32_t)l1 << 16);
                    size_t off = (((size_t)(b * NH + head)) * TSEQ + t) * HD + d0;
                    __nv_bfloat16* dh = (sect == 0) ? g_qh : (sect == 1) ? g_kh : g_vh;
                    __nv_bfloat16* dl = (sect == 0) ? g_ql : (sect == 1) ? g_kl : g_vl;
                    *(uint32_t*)&dh[off] = hv;
                    *(uint32_t*)&dl[off] = lv;
                } else {
                    *(float2*)&out[(size_t)m * CEMB + n] = make_float2(v0, v1);
                }
            }
        }
    }
}

// ---------------- HMMA block-sparse flash attention ---------------------------
#define SMQ_H  0
#define SMQ_L  18432
#define SMKV   36864
#define STAGEKV 73728
#define SST_OFF (SMKV + 2*STAGEKV)          // 184320
#define ATTN_SMEM2 (SST_OFF + 128*33*4)     // 201216

template <int NNI>
__device__ __forceinline__ void dense_block(
    uint32_t smb, uint32_t kst, int lane, int wid, int i0, int jb,
    float (&oacc)[8][4], float (&m)[2], float (&l)[2])
{
    const int NKK = NNI / 2;
    int g = lane >> 3, w = lane & 7;
    uint32_t arow = smb + SMQ_H + (wid * 16 + ((g & 1) << 3) + w) * 144;
    uint32_t ka = ((g >> 1) << 3) * 2;

    uint32_t qhf[4][4], qlf[4][4];
#pragma unroll
    for (int ks = 0; ks < 4; ks++) {
        ldmx4(qhf[ks], arow + ks * 32 + ka);
        ldmx4(qlf[ks], arow + 18432 + ks * 32 + ka);
    }

    float sacc[NNI][4];
#pragma unroll
    for (int ni = 0; ni < NNI; ni++)
#pragma unroll
        for (int q = 0; q < 4; q++) sacc[ni][q] = 0.f;

    uint32_t kboff = ((g & 1) << 3) * 2;
#pragma unroll
    for (int ni = 0; ni < NNI; ni++) {
        uint32_t brow = kst + (ni * 8 + w) * 144 + kboff;
#pragma unroll
        for (int ks = 0; ks < 4; ks++) {
            uint32_t bh2[2], bl2[2];
            ldmx2(bh2, brow + ks * 32);
            ldmx2(bl2, brow + 18432 + ks * 32);
            mma16816(sacc[ni], qhf[ks], bh2);
            mma16816(sacc[ni], qhf[ks], bl2);
            mma16816(sacc[ni], qlf[ks], bh2);
        }
    }

    int c0 = (lane & 3) * 2;
    float mb0 = -1e30f, mb1 = -1e30f;
#pragma unroll
    for (int ni = 0; ni < NNI; ni++) {
        int jB = jb + ni * 8 + c0;
#pragma unroll
        for (int q = 0; q < 4; q++) {
            int jj = jB + (q & 1);
            int ii = (q < 2) ? i0 : i0 + 8;
            int diff = ii - jj;
            bool ok = diff >= 0 &&
                      (diff < 256 || (diff & 127) == 0 || jj < 16);
            sacc[ni][q] = ok ? sacc[ni][q] * SCALE : -1e30f;
        }
        mb0 = fmaxf(mb0, fmaxf(sacc[ni][0], sacc[ni][1]));
        mb1 = fmaxf(mb1, fmaxf(sacc[ni][2], sacc[ni][3]));
    }
    mb0 = fmaxf(mb0, __shfl_xor_sync(0xffffffffu, mb0, 1));
    mb0 = fmaxf(mb0, __shfl_xor_sync(0xffffffffu, mb0, 2));
    mb1 = fmaxf(mb1, __shfl_xor_sync(0xffffffffu, mb1, 1));
    mb1 = fmaxf(mb1, __shfl_xor_sync(0xffffffffu, mb1, 2));

    float mn0 = fmaxf(m[0], mb0), mn1 = fmaxf(m[1], mb1);
    float cs0 = __expf(m[0] - mn0), cs1 = __expf(m[1] - mn1);
    float ls0 = 0.f, ls1 = 0.f;
#pragma unroll
    for (int ni = 0; ni < NNI; ni++) {
        float p0 = __expf(sacc[ni][0] - mn0);
        float p1 = __expf(sacc[ni][1] - mn0);
        float p2 = __expf(sacc[ni][2] - mn1);
        float p3 = __expf(sacc[ni][3] - mn1);
        sacc[ni][0] = p0; sacc[ni][1] = p1; sacc[ni][2] = p2; sacc[ni][3] = p3;
        ls0 += p0 + p1; ls1 += p2 + p3;
    }
    ls0 += __shfl_xor_sync(0xffffffffu, ls0, 1);
    ls0 += __shfl_xor_sync(0xffffffffu, ls0, 2);
    ls1 += __shfl_xor_sync(0xffffffffu, ls1, 1);
    ls1 += __shfl_xor_sync(0xffffffffu, ls1, 2);
    l[0] = l[0] * cs0 + ls0; m[0] = mn0;
    l[1] = l[1] * cs1 + ls1; m[1] = mn1;
#pragma unroll
    for (int nd = 0; nd < 8; nd++) {
        oacc[nd][0] *= cs0; oacc[nd][1] *= cs0;
        oacc[nd][2] *= cs1; oacc[nd][3] *= cs1;
    }

    uint32_t vbase = kst + 2 * 18432;
    int jrow = ((g & 1) << 3) + w;
    int dcol = ((g >> 1) << 3) * 2;
#pragma unroll
    for (int kk = 0; kk < NKK; kk++) {
        float* s0 = sacc[2 * kk];
        float* s1 = sacc[2 * kk + 1];
        float h00 = __bfloat162float(__float2bfloat16_rn(s0[0]));
        float h01 = __bfloat162float(__float2bfloat16_rn(s0[1]));
        float h02 = __bfloat162float(__float2bfloat16_rn(s0[2]));
        float h03 = __bfloat162float(__float2bfloat16_rn(s0[3]));
        float h10 = __bfloat162float(__float2bfloat16_rn(s1[0]));
        float h11 = __bfloat162float(__float2bfloat16_rn(s1[1]));
        float h12 = __bfloat162float(__float2bfloat16_rn(s1[2]));
        float h13 = __bfloat162float(__float2bfloat16_rn(s1[3]));
        uint32_t pah[4], pal[4];
        pah[0] = packbf(h00, h01); pah[1] = packbf(h02, h03);
        pah[2] = packbf(h10, h11); pah[3] = packbf(h12, h13);
        pal[0] = packbf(s0[0] - h00, s0[1] - h01);
        pal[1] = packbf(s0[2] - h02, s0[3] - h03);
        pal[2] = packbf(s1[0] - h10, s1[1] - h11);
        pal[3] = packbf(s1[2] - h12, s1[3] - h13);
#pragma unroll
        for (int nd2 = 0; nd2 < 4; nd2++) {
            uint32_t addr = vbase + (kk * 16 + jrow) * 144 + nd2 * 32 + dcol;
            uint32_t vh4[4], vl4[4];
            ldmx4t(vh4, addr);
            ldmx4t(vl4, addr + 18432);
            mma16816(oacc[nd2 * 2], pah, vh4);
            mma16816(oacc[nd2 * 2], pah, vl4);
            mma16816(oacc[nd2 * 2], pal, vh4);
            mma16816(oacc[nd2 * 2 + 1], pah, vh4 + 2);
            mma16816(oacc[nd2 * 2 + 1], pah, vl4 + 2);
            mma16816(oacc[nd2 * 2 + 1], pal, vh4 + 2);
        }
    }
}

__global__ __launch_bounds__(256, 1)
void attn_mma()
{
    extern __shared__ __align__(16) char sm[];
    uint32_t smb = smem_u32(sm);
    int tid = threadIdx.x, lane = tid & 31, wid = tid >> 5;
    int qb = blockIdx.x, bh = blockIdx.y;

    size_t qoff = ((size_t)bh * TSEQ + (size_t)qb * 128) * HD;
    for (int c = tid; c < 1024; c += 256) {
        int row = c >> 3, ch = c & 7;
        *(uint4*)(sm + SMQ_H + row * 144 + ch * 16) =
            *(const uint4*)&g_qh[qoff + row * HD + ch * 8];
        *(uint4*)(sm + SMQ_L + row * 144 + ch * 16) =
            *(const uint4*)&g_ql[qoff + row * HD + ch * 8];
    }

    float oacc[8][4];
#pragma unroll
    for (int nd = 0; nd < 8; nd++)
#pragma unroll
        for (int q = 0; q < 4; q++) oacc[nd][q] = 0.f;
    float m[2] = { -1e30f, -1e30f }, l[2] = { 0.f, 0.f };

    int kb_lo = (qb - 2 > 0) ? qb - 2 : 0;
    int blocks[4], bcols[4], ndense = 0;
    for (int kb = kb_lo; kb <= qb; kb++) { blocks[ndense] = kb; bcols[ndense] = 128; ndense++; }
    if (kb_lo > 0) { blocks[ndense] = 0; bcols[ndense] = 16; ndense++; }

    auto stage_kv = [&](int st, int idx) {
        int kb = blocks[idx];
        int nr = (bcols[idx] == 128) ? 128 : 16;
        uint32_t base = smb + SMKV + st * STAGEKV;
        const __nv_bfloat16* srcs[4] = { g_kh, g_kl, g_vh, g_vl };
#pragma unroll
        for (int mm = 0; mm < 4; mm++) {
            const __nv_bfloat16* src =
                srcs[mm] + ((size_t)bh * TSEQ + (size_t)kb * 128) * HD;
            for (int c = tid; c < nr * 8; c += 256) {
                int row = c >> 3, ch = c & 7;
                cpasync16(base + mm * 18432 + row * 144 + ch * 16,
                          src + row * HD + ch * 8);
            }
        }
    };

    stage_kv(0, 0); CP_COMMIT();
    int i0 = qb * 128 + wid * 16 + (lane >> 2);

    for (int it = 0; it < ndense; it++) {
        __syncthreads();
        if (it + 1 < ndense) { stage_kv((it + 1) & 1, it + 1); CP_COMMIT(); CP_WAIT1(); }
        else CP_WAIT0();
        __syncthreads();
        uint32_t kst = smb + SMKV + (it & 1) * STAGEKV;
        if (bcols[it] == 128)
            dense_block<16>(smb, kst, lane, wid, i0, blocks[it] * 128, oacc, m, l);
        else
            dense_block<2>(smb, kst, lane, wid, i0, blocks[it] * 128, oacc, m, l);
    }

    // strided diagonals
    int nkb = qb - 2;
    float* Sst = (float*)(sm + SST_OFF);
    if (nkb > 0) {
        int part = lane & 3;
        for (int pass = 0; pass < 2; pass++) {
            int rloc = wid * 16 + pass * 8 + (lane >> 2);
            for (int kb = 0; kb < nkb; kb++) {
                float sc;
                if (kb == 0 && rloc < 16) {
                    sc = -1e30f;
                } else {
                    int j = kb * 128 + rloc;
                    size_t kbase = ((size_t)bh * TSEQ + j) * HD + part * 16;
                    uint32_t qb0 = smb + SMQ_H + rloc * 144 + part * 32;
                    float sum = 0.f;
#pragma unroll
                    for (int seg = 0; seg < 2; seg++) {
                        uint32_t qh4[4], ql4[4];
                        asm volatile("ld.shared.v4.b32 {%0,%1,%2,%3}, [%4];"
                            : "=r"(qh4[0]), "=r"(qh4[1]), "=r"(qh4[2]), "=r"(qh4[3])
                            : "r"(qb0 + seg * 16));
                        asm volatile("ld.shared.v4.b32 {%0,%1,%2,%3}, [%4];"
                            : "=r"(ql4[0]), "=r"(ql4[1]), "=r"(ql4[2]), "=r"(ql4[3])
                            : "r"(qb0 + 18432 + seg * 16));
                        uint4 kh4 = *(const uint4*)&g_kh[kbase + seg * 8];
                        uint4 kl4 = *(const uint4*)&g_kl[kbase + seg * 8];
                        const uint32_t* khp = (const uint32_t*)&kh4;
                        const uint32_t* klp = (const uint32_t*)&kl4;
#pragma unroll
                        for (int u = 0; u < 4; u++) {
                            float2 qh2 = bf2f(qh4[u]), ql2 = bf2f(ql4[u]);
                            float2 kh2 = bf2f(khp[u]), kl2 = bf2f(klp[u]);
                            sum += (qh2.x + ql2.x) * (kh2.x + kl2.x);
                            sum += (qh2.y + ql2.y) * (kh2.y + kl2.y);
                        }
                    }
                    sum += __shfl_xor_sync(0xffffffffu, sum, 1);
                    sum += __shfl_xor_sync(0xffffffffu, sum, 2);
                    sc = sum * SCALE;
                }
                if (part == 0) Sst[rloc * 33 + kb] = sc;
            }
        }
        __syncwarp();

#pragma unroll
        for (int h = 0; h < 2; h++) {
            int r = wid * 16 + (lane >> 2) + h * 8;
            float mo = m[h], mx = mo;
            for (int kb = 0; kb < nkb; kb++)
                mx = fmaxf(mx, Sst[r * 33 + kb]);
            float cs = __expf(mo - mx);
            float ls = 0.f;
#pragma unroll
            for (int nd = 0; nd < 8; nd++) {
                oacc[nd][h * 2 + 0] *= cs;
                oacc[nd][h * 2 + 1] *= cs;
            }
            for (int kb = 0; kb < nkb; kb++) {
                float p = __expf(Sst[r * 33 + kb] - mx);
                ls += p;
                if (p > 0.f) {
                    int j = kb * 128 + r;
                    size_t vb = ((size_t)bh * TSEQ + j) * HD;
#pragma unroll
                    for (int nd = 0; nd < 8; nd++) {
                        int d0 = nd * 8 + (lane & 3) * 2;
                        float2 vh = bf2f(*(const uint32_t*)&g_vh[vb + d0]);
                        float2 vl = bf2f(*(const uint32_t*)&g_vl[vb + d0]);
                        oacc[nd][h * 2 + 0] += p * (vh.x + vl.x);
                        oacc[nd][h * 2 + 1] += p * (vh.y + vl.y);
                    }
                }
            }
            m[h] = mx;
            l[h] = l[h] * cs + ls;
        }
    }

    // epilogue: y -> hi/lo bf16
    int b = bh >> 4, head = bh & 15;
#pragma unroll
    for (int h = 0; h < 2; h++) {
        float inv = 1.f / l[h];
        int i = qb * 128 + wid * 16 + (lane >> 2) + h * 8;
        size_t row_off = ((size_t)(b * TSEQ + i)) * CEMB + head * HD;
#pragma unroll
        for (int nd = 0; nd < 8; nd++) {
            int d0 = nd * 8 + (lane & 3) * 2;
            float y0 = oacc[nd][h * 2 + 0] * inv;
            float y1 = oacc[nd][h * 2 + 1] * inv;
            unsigned short h0, l0, h1, l1;
            split1(y0, h0, l0); split1(y1, h1, l1);
            *(uint32_t*)&g_yh[row_off + d0] = (uint32_t)h0 | ((uint32_t)h1 << 16);
            *(uint32_t*)&g_yl[row_off + d0] = (uint32_t)l0 | ((uint32_t)l1 << 16);
        }
    }
}

// ---------------- launch -----------------------------------------------------
extern "C" void kernel_launch(void* const* d_in, const int* in_sizes, int n_in,
                              void* d_out, int out_size)
{
    const float* x      = (const float*)d_in[0];
    const float* w_qkv  = (const float*)d_in[1];
    const float* b_qkv  = (const float*)d_in[2];
    const float* w_proj = (const float*)d_in[3];
    const float* b_proj = (const float*)d_in[4];
    float* out = (float*)d_out;

    cudaFuncSetAttribute(gemm_mma<0>,
                         cudaFuncAttributeMaxDynamicSharedMemorySize, GSMEM);
    cudaFuncSetAttribute(gemm_mma<1>,
                         cudaFuncAttributeMaxDynamicSharedMemorySize, GSMEM);
    cudaFuncSetAttribute(attn_mma,
                         cudaFuncAttributeMaxDynamicSharedMemorySize, ATTN_SMEM2);

    int n_x = MROWS * CEMB;
    conv_split_x<<<n_x / 4 / 256, 256>>>(x, n_x);
    conv_split_T<0><<<dim3(3 * CEMB / 32, CEMB / 32), 256>>>(w_qkv, CEMB, 3 * CEMB);
    conv_split_T<1><<<dim3(CEMB / 32, CEMB / 32), 256>>>(w_proj, CEMB, CEMB);

    // 1) QKV GEMM -> Q/K/V bf16 hi/lo
    gemm_mma<0><<<dim3(3 * CEMB / 128, MROWS / 256), 512, GSMEM>>>(b_qkv, nullptr);

    // 2) HMMA block-sparse flash attention -> yh/yl
    attn_mma<<<dim3(TSEQ / 128, BATCH * NH), 256, ATTN_SMEM2>>>();

    // 3) output projection -> out
    gemm_mma<1><<<dim3(CEMB / 128, MROWS / 256), 512, GSMEM>>>(b_proj, out);
}

// round 6
// speedup vs baseline: 1.0433x; 1.0433x over previous
#include <cuda_runtime.h>
#include <cuda_bf16.h>
#include <cstdint>
#include <math.h>

#define BATCH 2
#define TSEQ  4096
#define NH    16
#define HD    64
#define CEMB  1024
#define MROWS (BATCH*TSEQ)          // 8192
#define SCALE 0.125f                // 1/sqrt(64)

// ---------------- scratch ------------------------------------------------------
__device__ __nv_bfloat16 g_xh[(size_t)MROWS*CEMB];
__device__ __nv_bfloat16 g_xl[(size_t)MROWS*CEMB];
__device__ __nv_bfloat16 g_yh[(size_t)MROWS*CEMB];
__device__ __nv_bfloat16 g_yl[(size_t)MROWS*CEMB];
__device__ __nv_bfloat16 g_wqh[(size_t)3*CEMB*CEMB];   // [N,K] K-major
__device__ __nv_bfloat16 g_wql[(size_t)3*CEMB*CEMB];
__device__ __nv_bfloat16 g_wph[(size_t)CEMB*CEMB];
__device__ __nv_bfloat16 g_wpl[(size_t)CEMB*CEMB];
__device__ __nv_bfloat16 g_qh[(size_t)BATCH*NH*TSEQ*HD];
__device__ __nv_bfloat16 g_ql[(size_t)BATCH*NH*TSEQ*HD];
__device__ __nv_bfloat16 g_kh[(size_t)BATCH*NH*TSEQ*HD];
__device__ __nv_bfloat16 g_kl[(size_t)BATCH*NH*TSEQ*HD];
__device__ __nv_bfloat16 g_vh[(size_t)BATCH*NH*TSEQ*HD];
__device__ __nv_bfloat16 g_vl[(size_t)BATCH*NH*TSEQ*HD];

// ---------------- PTX helpers --------------------------------------------------
__device__ __forceinline__ uint32_t smem_u32(const void* p) {
    uint32_t a;
    asm("{ .reg .u64 t; cvta.to.shared.u64 t, %1; cvt.u32.u64 %0, t; }"
        : "=r"(a) : "l"(p));
    return a;
}
__device__ __forceinline__ void cpasync16(uint32_t saddr, const void* g) {
    asm volatile("cp.async.cg.shared.global [%0], [%1], 16;"
                 :: "r"(saddr), "l"(g) : "memory");
}
#define CP_COMMIT() asm volatile("cp.async.commit_group;" ::: "memory")
#define CP_WAIT1()  asm volatile("cp.async.wait_group 1;" ::: "memory")
#define CP_WAIT0()  asm volatile("cp.async.wait_group 0;" ::: "memory")

__device__ __forceinline__ void ldmx4(uint32_t* r, uint32_t addr) {
    asm volatile("ldmatrix.sync.aligned.m8n8.x4.shared.b16 {%0,%1,%2,%3}, [%4];"
        : "=r"(r[0]), "=r"(r[1]), "=r"(r[2]), "=r"(r[3]) : "r"(addr));
}
__device__ __forceinline__ void ldmx2(uint32_t* r, uint32_t addr) {
    asm volatile("ldmatrix.sync.aligned.m8n8.x2.shared.b16 {%0,%1}, [%2];"
        : "=r"(r[0]), "=r"(r[1]) : "r"(addr));
}
__device__ __forceinline__ void ldmx4t(uint32_t* r, uint32_t addr) {
    asm volatile("ldmatrix.sync.aligned.m8n8.x4.trans.shared.b16 {%0,%1,%2,%3}, [%4];"
        : "=r"(r[0]), "=r"(r[1]), "=r"(r[2]), "=r"(r[3]) : "r"(addr));
}
__device__ __forceinline__ void mma16816(float* d, const uint32_t* a,
                                         const uint32_t* b) {
    asm volatile(
        "mma.sync.aligned.m16n8k16.row.col.f32.bf16.bf16.f32 "
        "{%0,%1,%2,%3}, {%4,%5,%6,%7}, {%8,%9}, {%0,%1,%2,%3};"
        : "+f"(d[0]), "+f"(d[1]), "+f"(d[2]), "+f"(d[3])
        : "r"(a[0]), "r"(a[1]), "r"(a[2]), "r"(a[3]), "r"(b[0]), "r"(b[1]));
}

__device__ __forceinline__ float2 bf2f(uint32_t u) {
    __nv_bfloat162 b = *(__nv_bfloat162*)&u;
    return __bfloat1622float2(b);
}
__device__ __forceinline__ uint32_t packbf(float x, float y) {
    __nv_bfloat162 t = __floats2bfloat162_rn(x, y);
    return *(uint32_t*)&t;
}
__device__ __forceinline__ void split1(float v, unsigned short& h, unsigned short& l) {
    __nv_bfloat16 hb = __float2bfloat16_rn(v);
    __nv_bfloat16 lb = __float2bfloat16_rn(v - __bfloat162float(hb));
    h = __bfloat16_as_ushort(hb);
    l = __bfloat16_as_ushort(lb);
}

// ---------------- conversion kernels -------------------------------------------
__global__ void conv_split_x(const float* __restrict__ src, int n) {
    int i = (blockIdx.x * 256 + threadIdx.x) * 4;
    if (i < n) {
        float4 v = *(const float4*)&src[i];
        ushort4 h, l;
        split1(v.x, h.x, l.x); split1(v.y, h.y, l.y);
        split1(v.z, h.z, l.z); split1(v.w, h.w, l.w);
        *(ushort4*)&g_xh[i] = h;
        *(ushort4*)&g_xl[i] = l;
    }
}
template <int W>
__global__ void conv_split_T(const float* __restrict__ w, int K, int N) {
    __shared__ float t[32][33];
    __nv_bfloat16* hiT = (W == 0) ? g_wqh : g_wph;
    __nv_bfloat16* loT = (W == 0) ? g_wql : g_wpl;
    int n0 = blockIdx.x * 32, k0 = blockIdx.y * 32;
    int tx = threadIdx.x & 31, ty = threadIdx.x >> 5;
    for (int r = ty; r < 32; r += 8)
        t[r][tx] = w[(size_t)(k0 + r) * N + n0 + tx];
    __syncthreads();
    for (int r = ty; r < 32; r += 8) {
        float v = t[tx][r];
        unsigned short h, l;
        split1(v, h, l);
        size_t o = (size_t)(n0 + r) * K + k0 + tx;
        hiT[o] = __ushort_as_bfloat16(h);
        loT[o] = __ushort_as_bfloat16(l);
    }
}

// ---------------- bf16x3 GEMM: CTA 128x256, 8 warps of 64x64 -------------------
#define BK    64
#define ROWB  144                   // 72 bf16 padded rows
#define A_MATB (128*ROWB)           // 18432
#define B_MATB (256*ROWB)           // 36864
#define STAGEB (2*A_MATB + 2*B_MATB)  // 110592
#define GSMEM (2*STAGEB)            // 221184

template <int MODE>
__global__ __launch_bounds__(256, 1)
void gemm_mma(const float* __restrict__ bias, float* __restrict__ out)
{
    extern __shared__ __align__(16) char sm[];
    uint32_t smb = smem_u32(sm);

    const __nv_bfloat16* Ah = (MODE == 0) ? g_xh : g_yh;
    const __nv_bfloat16* Al = (MODE == 0) ? g_xl : g_yl;
    const __nv_bfloat16* Bh = (MODE == 0) ? g_wqh : g_wph;
    const __nv_bfloat16* Bl = (MODE == 0) ? g_wql : g_wpl;

    int tid = threadIdx.x;
    int wid = tid >> 5, lane = tid & 31;
    int wm = wid >> 2, wn = wid & 3;          // 2 x 4 warps, warp tile 64x64
    int mBase = blockIdx.y * 128, nBase = blockIdx.x * 256;

    float acc[4][8][4];
#pragma unroll
    for (int mi = 0; mi < 4; mi++)
#pragma unroll
        for (int ni = 0; ni < 8; ni++)
#pragma unroll
            for (int q = 0; q < 4; q++) acc[mi][ni][q] = 0.f;

    auto load_stage = [&](int st, int kt) {
        int k0 = kt * BK;
        uint32_t sb = smb + st * STAGEB;
        // A hi/lo: 128 rows
#pragma unroll
        for (int c = tid; c < 1024; c += 256) {
            int row = c >> 3, ch = c & 7;
            size_t g = (size_t)(mBase + row) * CEMB + k0 + ch * 8;
            cpasync16(sb + row * ROWB + ch * 16, Ah + g);
            cpasync16(sb + A_MATB + row * ROWB + ch * 16, Al + g);
        }
        // B hi/lo: 256 rows
#pragma unroll
        for (int c = tid; c < 2048; c += 256) {
            int row = c >> 3, ch = c & 7;
            size_t g = (size_t)(nBase + row) * CEMB + k0 + ch * 8;
            cpasync16(sb + 2 * A_MATB + row * ROWB + ch * 16, Bh + g);
            cpasync16(sb + 2 * A_MATB + B_MATB + row * ROWB + ch * 16, Bl + g);
        }
    };

    int g = lane >> 3, w = lane & 7;
    uint32_t a_row = (wm * 64 + ((g & 1) << 3) + w) * ROWB;
    uint32_t b_row = (wn * 64 + ((g >> 1) << 3) + w) * ROWB;
    uint32_t ka_off = (g >> 1) * 16;
    uint32_t kb_off = (g & 1) * 16;

    load_stage(0, 0); CP_COMMIT();

    for (int kt = 0; kt < 16; kt++) {
        CP_WAIT0();
        __syncthreads();
        if (kt + 1 < 16) { load_stage((kt + 1) & 1, kt + 1); CP_COMMIT(); }

        int s = kt & 1;
        uint32_t bAh = smb + s * STAGEB;
        uint32_t bAl = bAh + A_MATB;
        uint32_t bBh = bAl + A_MATB;
        uint32_t bBl = bBh + B_MATB;

#pragma unroll
        for (int ks0 = 0; ks0 < 4; ks0++) {
            int ks = (ks0 + wid) & 3;         // stagger LDSM bursts across warps
            uint32_t koff = ks * 32;
            uint32_t ah[4][4], al[4][4];
#pragma unroll
            for (int mi = 0; mi < 4; mi++) {
                uint32_t ro = a_row + mi * 16 * ROWB + koff + ka_off;
                ldmx4(ah[mi], bAh + ro);
                ldmx4(al[mi], bAl + ro);
            }
#pragma unroll
            for (int np = 0; np < 4; np++) {
                uint32_t ro = b_row + np * 16 * ROWB + koff + kb_off;
                uint32_t bh4[4], bl4[4];
                ldmx4(bh4, bBh + ro);
                ldmx4(bl4, bBl + ro);
#pragma unroll
                for (int mi = 0; mi < 4; mi++) {
                    mma16816(acc[mi][2*np],   ah[mi], bh4);
                    mma16816(acc[mi][2*np],   ah[mi], bl4);
                    mma16816(acc[mi][2*np],   al[mi], bh4);
                    mma16816(acc[mi][2*np+1], ah[mi], bh4 + 2);
                    mma16816(acc[mi][2*np+1], ah[mi], bl4 + 2);
                    mma16816(acc[mi][2*np+1], al[mi], bh4 + 2);
                }
            }
        }
        __syncthreads();
    }

    // epilogue
    int r_in = lane >> 2, c_in = (lane & 3) * 2;
#pragma unroll
    for (int mi = 0; mi < 4; mi++) {
#pragma unroll
        for (int half = 0; half < 2; half++) {
            int m = mBase + wm * 64 + mi * 16 + r_in + half * 8;
#pragma unroll
            for (int ni = 0; ni < 8; ni++) {
                int n = nBase + wn * 64 + ni * 8 + c_in;
                float v0 = acc[mi][ni][half * 2 + 0] + bias[n];
                float v1 = acc[mi][ni][half * 2 + 1] + bias[n + 1];
                if (MODE == 0) {
                    int b = m >> 12, t = m & 4095;
                    int sect = n >> 10, cc = n & 1023;
                    int head = cc >> 6, d0 = cc & 63;
                    unsigned short h0, l0, h1, l1;
                    split1(v0, h0, l0); split1(v1, h1, l1);
                    uint32_t hv = (uint32_t)h0 | ((uint32_t)h1 << 16);
                    uint32_t lv = (uint32_t)l0 | ((uint32_t)l1 << 16);
                    size_t off = (((size_t)(b * NH + head)) * TSEQ + t) * HD + d0;
                    __nv_bfloat16* dh = (sect == 0) ? g_qh : (sect == 1) ? g_kh : g_vh;
                    __nv_bfloat16* dl = (sect == 0) ? g_ql : (sect == 1) ? g_kl : g_vl;
                    *(uint32_t*)&dh[off] = hv;
                    *(uint32_t*)&dl[off] = lv;
                } else {
                    *(float2*)&out[(size_t)m * CEMB + n] = make_float2(v0, v1);
                }
            }
        }
    }
}

// ---------------- HMMA block-sparse flash attention (512 thr, col-split) ------
#define SMQ_H  0
#define SMQ_L  18432
#define SMKV   36864
#define STAGEKV 73728
#define SST_OFF (SMKV + 2*STAGEKV)          // 184320
#define ATTN_SMEM2 (SST_OFF + 128*33*4)     // 201216
#define MERGE_B 4352                        // per-warp merge slab at SMKV

template <int NNI>
__device__ __forceinline__ void dense_block(
    uint32_t smb, uint32_t kst, int lane, int rg, int colbase, int i0, int jb,
    float (&oacc)[8][4], float (&m)[2], float (&l)[2])
{
    const int NKK = NNI / 2;
    int g = lane >> 3, w = lane & 7;
    uint32_t arow = smb + SMQ_H + (rg * 16 + ((g & 1) << 3) + w) * 144;
    uint32_t ka = (g >> 1) * 16;
    uint32_t kboff = (g & 1) * 16;

    float sacc[NNI][4];
#pragma unroll
    for (int ni = 0; ni < NNI; ni++)
#pragma unroll
        for (int q = 0; q < 4; q++) sacc[ni][q] = 0.f;

#pragma unroll
    for (int ks = 0; ks < 4; ks++) {
        uint32_t qh4[4], ql4[4];
        ldmx4(qh4, arow + ks * 32 + ka);
        ldmx4(ql4, arow + 18432 + ks * 32 + ka);
#pragma unroll
        for (int ni = 0; ni < NNI; ni++) {
            uint32_t brow = kst + (colbase + ni * 8 + w) * 144 + kboff + ks * 32;
            uint32_t bh2[2], bl2[2];
            ldmx2(bh2, brow);
            ldmx2(bl2, brow + 18432);
            mma16816(sacc[ni], qh4, bh2);
            mma16816(sacc[ni], qh4, bl2);
            mma16816(sacc[ni], ql4, bh2);
        }
    }

    int c0 = (lane & 3) * 2;
    float mb0 = -1e30f, mb1 = -1e30f;
#pragma unroll
    for (int ni = 0; ni < NNI; ni++) {
        int jB = jb + ni * 8 + c0;
#pragma unroll
        for (int q = 0; q < 4; q++) {
            int jj = jB + (q & 1);
            int ii = (q < 2) ? i0 : i0 + 8;
            int diff = ii - jj;
            bool ok = diff >= 0 &&
                      (diff < 256 || (diff & 127) == 0 || jj < 16);
            sacc[ni][q] = ok ? sacc[ni][q] * SCALE : -1e30f;
        }
        mb0 = fmaxf(mb0, fmaxf(sacc[ni][0], sacc[ni][1]));
        mb1 = fmaxf(mb1, fmaxf(sacc[ni][2], sacc[ni][3]));
    }
    mb0 = fmaxf(mb0, __shfl_xor_sync(0xffffffffu, mb0, 1));
    mb0 = fmaxf(mb0, __shfl_xor_sync(0xffffffffu, mb0, 2));
    mb1 = fmaxf(mb1, __shfl_xor_sync(0xffffffffu, mb1, 1));
    mb1 = fmaxf(mb1, __shfl_xor_sync(0xffffffffu, mb1, 2));

    // clamp: if everything (incl. running max) is masked, probs flush to 0
    float mn0 = fmaxf(fmaxf(m[0], mb0), -1e28f);
    float mn1 = fmaxf(fmaxf(m[1], mb1), -1e28f);
    float cs0 = __expf(m[0] - mn0), cs1 = __expf(m[1] - mn1);
    float ls0 = 0.f, ls1 = 0.f;
#pragma unroll
    for (int ni = 0; ni < NNI; ni++) {
        float p0 = __expf(sacc[ni][0] - mn0);
        float p1 = __expf(sacc[ni][1] - mn0);
        float p2 = __expf(sacc[ni][2] - mn1);
        float p3 = __expf(sacc[ni][3] - mn1);
        sacc[ni][0] = p0; sacc[ni][1] = p1; sacc[ni][2] = p2; sacc[ni][3] = p3;
        ls0 += p0 + p1; ls1 += p2 + p3;
    }
    ls0 += __shfl_xor_sync(0xffffffffu, ls0, 1);
    ls0 += __shfl_xor_sync(0xffffffffu, ls0, 2);
    ls1 += __shfl_xor_sync(0xffffffffu, ls1, 1);
    ls1 += __shfl_xor_sync(0xffffffffu, ls1, 2);
    l[0] = l[0] * cs0 + ls0; m[0] = mn0;
    l[1] = l[1] * cs1 + ls1; m[1] = mn1;
#pragma unroll
    for (int nd = 0; nd < 8; nd++) {
        oacc[nd][0] *= cs0; oacc[nd][1] *= cs0;
        oacc[nd][2] *= cs1; oacc[nd][3] *= cs1;
    }

    uint32_t vbase = kst + 2 * 18432;
    int jrow = ((g & 1) << 3) + w;
    int dcol = (g >> 1) * 16;
#pragma unroll
    for (int kk = 0; kk < NKK; kk++) {
        float* s0 = sacc[2 * kk];
        float* s1 = sacc[2 * kk + 1];
        float h00 = __bfloat162float(__float2bfloat16_rn(s0[0]));
        float h01 = __bfloat162float(__float2bfloat16_rn(s0[1]));
        float h02 = __bfloat162float(__float2bfloat16_rn(s0[2]));
        float h03 = __bfloat162float(__float2bfloat16_rn(s0[3]));
        float h10 = __bfloat162float(__float2bfloat16_rn(s1[0]));
        float h11 = __bfloat162float(__float2bfloat16_rn(s1[1]));
        float h12 = __bfloat162float(__float2bfloat16_rn(s1[2]));
        float h13 = __bfloat162float(__float2bfloat16_rn(s1[3]));
        uint32_t pah[4], pal[4];
        pah[0] = packbf(h00, h01); pah[1] = packbf(h02, h03);
        pah[2] = packbf(h10, h11); pah[3] = packbf(h12, h13);
        pal[0] = packbf(s0[0] - h00, s0[1] - h01);
        pal[1] = packbf(s0[2] - h02, s0[3] - h03);
        pal[2] = packbf(s1[0] - h10, s1[1] - h11);
        pal[3] = packbf(s1[2] - h12, s1[3] - h13);
#pragma unroll
        for (int nd2 = 0; nd2 < 4; nd2++) {
            uint32_t addr = vbase + (colbase + kk * 16 + jrow) * 144 + nd2 * 32 + dcol;
            uint32_t vh4[4], vl4[4];
            ldmx4t(vh4, addr);
            ldmx4t(vl4, addr + 18432);
            mma16816(oacc[nd2 * 2], pah, vh4);
            mma16816(oacc[nd2 * 2], pah, vl4);
            mma16816(oacc[nd2 * 2], pal, vh4);
            mma16816(oacc[nd2 * 2 + 1], pah, vh4 + 2);
            mma16816(oacc[nd2 * 2 + 1], pah, vl4 + 2);
            mma16816(oacc[nd2 * 2 + 1], pal, vh4 + 2);
        }
    }
}

__global__ __launch_bounds__(512, 1)
void attn_mma()
{
    extern __shared__ __align__(16) char sm[];
    uint32_t smb = smem_u32(sm);
    int tid = threadIdx.x, lane = tid & 31, wid = tid >> 5;
    int rg = wid >> 1, ch2 = wid & 1;   // 8 row-groups x 2 col-halves
    int qb = blockIdx.x, bh = blockIdx.y;

    size_t qoff = ((size_t)bh * TSEQ + (size_t)qb * 128) * HD;
    for (int c = tid; c < 1024; c += 512) {
        int row = c >> 3, ch = c & 7;
        *(uint4*)(sm + SMQ_H + row * 144 + ch * 16) =
            *(const uint4*)&g_qh[qoff + row * HD + ch * 8];
        *(uint4*)(sm + SMQ_L + row * 144 + ch * 16) =
            *(const uint4*)&g_ql[qoff + row * HD + ch * 8];
    }

    float oacc[8][4];
#pragma unroll
    for (int nd = 0; nd < 8; nd++)
#pragma unroll
        for (int q = 0; q < 4; q++) oacc[nd][q] = 0.f;
    float m[2] = { -1e30f, -1e30f }, l[2] = { 0.f, 0.f };

    int kb_lo = (qb - 2 > 0) ? qb - 2 : 0;
    int blocks[4], bcols[4], ndense = 0;
    for (int kb = kb_lo; kb <= qb; kb++) { blocks[ndense] = kb; bcols[ndense] = 128; ndense++; }
    if (kb_lo > 0) { blocks[ndense] = 0; bcols[ndense] = 16; ndense++; }

    auto stage_kv = [&](int st, int idx) {
        int kb = blocks[idx];
        int nr = (bcols[idx] == 128) ? 128 : 16;
        uint32_t base = smb + SMKV + st * STAGEKV;
        const __nv_bfloat16* srcs[4] = { g_kh, g_kl, g_vh, g_vl };
#pragma unroll
        for (int mm = 0; mm < 4; mm++) {
            const __nv_bfloat16* src =
                srcs[mm] + ((size_t)bh * TSEQ + (size_t)kb * 128) * HD;
            for (int c = tid; c < nr * 8; c += 512) {
                int row = c >> 3, ch = c & 7;
                cpasync16(base + mm * 18432 + row * 144 + ch * 16,
                          src + row * HD + ch * 8);
            }
        }
    };

    stage_kv(0, 0); CP_COMMIT();
    int i0 = qb * 128 + rg * 16 + (lane >> 2);

    for (int it = 0; it < ndense; it++) {
        __syncthreads();
        if (it + 1 < ndense) { stage_kv((it + 1) & 1, it + 1); CP_COMMIT(); CP_WAIT1(); }
        else CP_WAIT0();
        __syncthreads();
        uint32_t kst = smb + SMKV + (it & 1) * STAGEKV;
        if (bcols[it] == 128)
            dense_block<8>(smb, kst, lane, rg, ch2 * 64, i0,
                           blocks[it] * 128 + ch2 * 64, oacc, m, l);
        else if (ch2 == 0)
            dense_block<2>(smb, kst, lane, rg, 0, i0, 0, oacc, m, l);
    }

    // strided diagonals: warp pair splits kb even/odd
    int nkb = qb - 2;
    float* Sst = (float*)(sm + SST_OFF);
    if (nkb > 0) {
        int part = lane & 3;
        for (int pass = 0; pass < 2; pass++) {
            int rloc = rg * 16 + pass * 8 + (lane >> 2);
            for (int kb = ch2; kb < nkb; kb += 2) {
                float sc;
                if (kb == 0 && rloc < 16) {
                    sc = -1e30f;
                } else {
                    int j = kb * 128 + rloc;
                    size_t kbase = ((size_t)bh * TSEQ + j) * HD + part * 16;
                    uint32_t qb0 = smb + SMQ_H + rloc * 144 + part * 32;
                    float sum = 0.f;
#pragma unroll
                    for (int seg = 0; seg < 2; seg++) {
                        uint32_t qh4[4], ql4[4];
                        asm volatile("ld.shared.v4.b32 {%0,%1,%2,%3}, [%4];"
                            : "=r"(qh4[0]), "=r"(qh4[1]), "=r"(qh4[2]), "=r"(qh4[3])
                            : "r"(qb0 + seg * 16));
                        asm volatile("ld.shared.v4.b32 {%0,%1,%2,%3}, [%4];"
                            : "=r"(ql4[0]), "=r"(ql4[1]), "=r"(ql4[2]), "=r"(ql4[3])
                            : "r"(qb0 + 18432 + seg * 16));
                        uint4 kh4 = *(const uint4*)&g_kh[kbase + seg * 8];
                        uint4 kl4 = *(const uint4*)&g_kl[kbase + seg * 8];
                        const uint32_t* khp = (const uint32_t*)&kh4;
                        const uint32_t* klp = (const uint32_t*)&kl4;
#pragma unroll
                        for (int u = 0; u < 4; u++) {
                            float2 qh2 = bf2f(qh4[u]), ql2 = bf2f(ql4[u]);
                            float2 kh2 = bf2f(khp[u]), kl2 = bf2f(klp[u]);
                            sum += (qh2.x + ql2.x) * (kh2.x + kl2.x);
                            sum += (qh2.y + ql2.y) * (kh2.y + kl2.y);
                        }
                    }
                    sum += __shfl_xor_sync(0xffffffffu, sum, 1);
                    sum += __shfl_xor_sync(0xffffffffu, sum, 2);
                    sc = sum * SCALE;
                }
                if (part == 0) Sst[rloc * 33 + kb] = sc;
            }
        }
        __syncwarp();

#pragma unroll
        for (int h = 0; h < 2; h++) {
            int r = rg * 16 + (lane >> 2) + h * 8;
            float mo = m[h], mx = mo;
            for (int kb = ch2; kb < nkb; kb += 2)
                mx = fmaxf(mx, Sst[r * 33 + kb]);
            mx = fmaxf(mx, -1e28f);
            float cs = __expf(mo - mx);
            float ls = 0.f;
#pragma unroll
            for (int nd = 0; nd < 8; nd++) {
                oacc[nd][h * 2 + 0] *= cs;
                oacc[nd][h * 2 + 1] *= cs;
            }
            for (int kb = ch2; kb < nkb; kb += 2) {
                float p = __expf(Sst[r * 33 + kb] - mx);
                ls += p;
                if (p > 0.f) {
                    int j = kb * 128 + r;
                    size_t vb = ((size_t)bh * TSEQ + j) * HD;
#pragma unroll
                    for (int nd = 0; nd < 8; nd++) {
                        int d0 = nd * 8 + (lane & 3) * 2;
                        float2 vh = bf2f(*(const uint32_t*)&g_vh[vb + d0]);
                        float2 vl = bf2f(*(const uint32_t*)&g_vl[vb + d0]);
                        oacc[nd][h * 2 + 0] += p * (vh.x + vl.x);
                        oacc[nd][h * 2 + 1] += p * (vh.y + vl.y);
                    }
                }
            }
            m[h] = mx;
            l[h] = l[h] * cs + ls;
        }
    }

    // pairwise split-softmax merge through smem, then epilogue
    __syncthreads();
    {
        char* mb = sm + SMKV + wid * MERGE_B;
#pragma unroll
        for (int h = 0; h < 2; h++) {
            int row = (lane >> 2) + h * 8;
#pragma unroll
            for (int nd = 0; nd < 8; nd++) {
                int col = nd * 8 + (lane & 3) * 2;
                *(float2*)(mb + (row * 64 + col) * 4) =
                    make_float2(oacc[nd][h * 2], oacc[nd][h * 2 + 1]);
            }
            if ((lane & 3) == 0)
                *(float2*)(mb + 4096 + row * 8) = make_float2(m[h], l[h]);
        }
    }
    __syncthreads();
    if (ch2 == 0) {
        char* pb = sm + SMKV + (wid + 1) * MERGE_B;
        int b = bh >> 4, head = bh & 15;
#pragma unroll
        for (int h = 0; h < 2; h++) {
            int row = (lane >> 2) + h * 8;
            float2 ml = *(float2*)(pb + 4096 + row * 8);
            float mx = fmaxf(m[h], ml.x);
            float f0 = __expf(m[h] - mx), f1 = __expf(ml.x - mx);
            float L = l[h] * f0 + ml.y * f1;
            float inv = 1.f / L;
            int i = qb * 128 + rg * 16 + row;
            size_t row_off = ((size_t)(b * TSEQ + i)) * CEMB + head * HD;
#pragma unroll
            for (int nd = 0; nd < 8; nd++) {
                int col = nd * 8 + (lane & 3) * 2;
                float2 o1 = *(float2*)(pb + (row * 64 + col) * 4);
                float y0 = (oacc[nd][h * 2 + 0] * f0 + o1.x * f1) * inv;
                float y1 = (oacc[nd][h * 2 + 1] * f0 + o1.y * f1) * inv;
                unsigned short h0, l0, h1, l1;
                split1(y0, h0, l0); split1(y1, h1, l1);
                *(uint32_t*)&g_yh[row_off + col] = (uint32_t)h0 | ((uint32_t)h1 << 16);
                *(uint32_t*)&g_yl[row_off + col] = (uint32_t)l0 | ((uint32_t)l1 << 16);
            }
        }
    }
}

// ---------------- launch -------------------------------------------------------
extern "C" void kernel_launch(void* const* d_in, const int* in_sizes, int n_in,
                              void* d_out, int out_size)
{
    const float* x      = (const float*)d_in[0];
    const float* w_qkv  = (const float*)d_in[1];
    const float* b_qkv  = (const float*)d_in[2];
    const float* w_proj = (const float*)d_in[3];
    const float* b_proj = (const float*)d_in[4];
    float* out = (float*)d_out;

    cudaFuncSetAttribute(gemm_mma<0>,
                         cudaFuncAttributeMaxDynamicSharedMemorySize, GSMEM);
    cudaFuncSetAttribute(gemm_mma<1>,
                         cudaFuncAttributeMaxDynamicSharedMemorySize, GSMEM);
    cudaFuncSetAttribute(attn_mma,
                         cudaFuncAttributeMaxDynamicSharedMemorySize, ATTN_SMEM2);

    int n_x = MROWS * CEMB;
    conv_split_x<<<n_x / 4 / 256, 256>>>(x, n_x);
    conv_split_T<0><<<dim3(3 * CEMB / 32, CEMB / 32), 256>>>(w_qkv, CEMB, 3 * CEMB);
    conv_split_T<1><<<dim3(CEMB / 32, CEMB / 32), 256>>>(w_proj, CEMB, CEMB);

    // 1) QKV GEMM -> Q/K/V bf16 hi/lo
    gemm_mma<0><<<dim3(3 * CEMB / 256, MROWS / 128), 256, GSMEM>>>(b_qkv, nullptr);

    // 2) HMMA block-sparse flash attention -> yh/yl
    attn_mma<<<dim3(TSEQ / 128, BATCH * NH), 512, ATTN_SMEM2>>>();

    // 3) output projection -> out
    gemm_mma<1><<<dim3(CEMB / 256, MROWS / 128), 256, GSMEM>>>(b_proj, out);
}